// round 1
// baseline (speedup 1.0000x reference)
#include <cuda_runtime.h>

#define NB 4
#define NS 2048
#define NE 512
#define NH 8
#define ND 64
#define NBH (NB*NH)

// Scratch (static device globals: allocation-guard safe)
__device__ float g_q[(size_t)NBH*NS*ND];      // [B,H,S,D]
__device__ float g_k[(size_t)NBH*NS*ND];
__device__ float g_v[(size_t)NBH*NS*ND];
__device__ float g_ctx[(size_t)NB*NS*NE];     // [B,S,H*D]
__device__ float g_proj[(size_t)NB*NS*NE];    // pre-LN output
__device__ float g_attn_fb[(size_t)NBH*NS*NS];// fallback if d_out lacks attn region

// ---------------------------------------------------------------------------
// GEMM: X[8192,512] @ W[512,512] + bias
// outsel: 0/1/2 -> g_q/g_k/g_v in [B,H,S,D] layout; 3 -> g_proj row-major.
// Xext==nullptr -> use g_ctx as input (output projection).
// 64x64 tile, BK=16, 256 threads, 4x4 register micro-tile.
// ---------------------------------------------------------------------------
__global__ void __launch_bounds__(256)
k_proj(const float* __restrict__ Xext, const float* __restrict__ W,
       const float* __restrict__ bias, int outsel)
{
    const float* X = Xext ? Xext : g_ctx;
    float* out;
    if (outsel == 0) out = g_q;
    else if (outsel == 1) out = g_k;
    else if (outsel == 2) out = g_v;
    else out = g_proj;

    __shared__ float As[16][64];
    __shared__ float Bs[16][64];

    const int tx = threadIdx.x, ty = threadIdx.y;
    const int tid = ty * 16 + tx;
    const int m0 = blockIdx.y * 64, n0 = blockIdx.x * 64;

    const int ar = tid >> 2, ak = (tid & 3) << 2;   // A: 64 rows x 16 k
    const int br = tid >> 4, bc = (tid & 15) << 2;  // B: 16 k x 64 n

    float acc[4][4];
    #pragma unroll
    for (int i = 0; i < 4; i++)
        #pragma unroll
        for (int j = 0; j < 4; j++) acc[i][j] = 0.f;

    for (int k0 = 0; k0 < NE; k0 += 16) {
        float4 av = *(const float4*)&X[(size_t)(m0 + ar) * NE + k0 + ak];
        As[ak+0][ar] = av.x; As[ak+1][ar] = av.y;
        As[ak+2][ar] = av.z; As[ak+3][ar] = av.w;
        *(float4*)&Bs[br][bc] = *(const float4*)&W[(size_t)(k0 + br) * NE + n0 + bc];
        __syncthreads();
        #pragma unroll
        for (int k = 0; k < 16; k++) {
            float4 a = *(const float4*)&As[k][ty * 4];
            float4 b = *(const float4*)&Bs[k][tx * 4];
            float aa[4] = {a.x, a.y, a.z, a.w};
            float bb[4] = {b.x, b.y, b.z, b.w};
            #pragma unroll
            for (int i = 0; i < 4; i++)
                #pragma unroll
                for (int j = 0; j < 4; j++)
                    acc[i][j] = fmaf(aa[i], bb[j], acc[i][j]);
        }
        __syncthreads();
    }

    float4 b4 = *(const float4*)&bias[n0 + tx * 4];
    float bb[4] = {b4.x, b4.y, b4.z, b4.w};
    #pragma unroll
    for (int i = 0; i < 4; i++) {
        int m = m0 + ty * 4 + i;
        float4 r;
        r.x = acc[i][0] + bb[0]; r.y = acc[i][1] + bb[1];
        r.z = acc[i][2] + bb[2]; r.w = acc[i][3] + bb[3];
        if (outsel < 3) {
            int b = m >> 11, s = m & (NS - 1);
            int h = n0 >> 6;  // N-tile == one head (64 cols)
            *(float4*)&out[(((size_t)(b * NH + h)) * NS + s) * ND + tx * 4] = r;
        } else {
            *(float4*)&out[(size_t)m * NE + n0 + tx * 4] = r;
        }
    }
}

// ---------------------------------------------------------------------------
// Scores: attn_raw[bh,qi,kj] = dot(q,k)/8, masked.  64x64 tile, K=64 (BK=16).
// ---------------------------------------------------------------------------
__global__ void __launch_bounds__(256)
k_scores(const unsigned char* __restrict__ mask, float* attn)
{
    if (!attn) attn = g_attn_fb;
    const int bh = blockIdx.z, b = bh >> 3;
    const float* qp = g_q + (size_t)bh * NS * ND + (size_t)blockIdx.y * 64 * ND;
    const float* kp = g_k + (size_t)bh * NS * ND + (size_t)blockIdx.x * 64 * ND;

    __shared__ float Qs[16][64];
    __shared__ float Ks[16][64];

    const int tx = threadIdx.x, ty = threadIdx.y;
    const int tid = ty * 16 + tx;
    const int ar = tid >> 2, ak = (tid & 3) << 2;

    float acc[4][4];
    #pragma unroll
    for (int i = 0; i < 4; i++)
        #pragma unroll
        for (int j = 0; j < 4; j++) acc[i][j] = 0.f;

    for (int k0 = 0; k0 < ND; k0 += 16) {
        float4 qv = *(const float4*)&qp[(size_t)ar * ND + k0 + ak];
        Qs[ak+0][ar] = qv.x; Qs[ak+1][ar] = qv.y;
        Qs[ak+2][ar] = qv.z; Qs[ak+3][ar] = qv.w;
        float4 kv = *(const float4*)&kp[(size_t)ar * ND + k0 + ak];
        Ks[ak+0][ar] = kv.x; Ks[ak+1][ar] = kv.y;
        Ks[ak+2][ar] = kv.z; Ks[ak+3][ar] = kv.w;
        __syncthreads();
        #pragma unroll
        for (int k = 0; k < 16; k++) {
            float4 a = *(const float4*)&Qs[k][ty * 4];
            float4 c = *(const float4*)&Ks[k][tx * 4];
            float aa[4] = {a.x, a.y, a.z, a.w};
            float cc[4] = {c.x, c.y, c.z, c.w};
            #pragma unroll
            for (int i = 0; i < 4; i++)
                #pragma unroll
                for (int j = 0; j < 4; j++)
                    acc[i][j] = fmaf(aa[i], cc[j], acc[i][j]);
        }
        __syncthreads();
    }

    const int qi0 = blockIdx.y * 64;
    const int kj0 = blockIdx.x * 64 + tx * 4;
    #pragma unroll
    for (int i = 0; i < 4; i++) {
        int qi = qi0 + ty * 4 + i;
        uchar4 mv = *(const uchar4*)&mask[((size_t)b * NS + qi) * NS + kj0];
        float4 r;
        r.x = mv.x ? -1e9f : acc[i][0] * 0.125f;
        r.y = mv.y ? -1e9f : acc[i][1] * 0.125f;
        r.z = mv.z ? -1e9f : acc[i][2] * 0.125f;
        r.w = mv.w ? -1e9f : acc[i][3] * 0.125f;
        *(float4*)&attn[((size_t)bh * NS + qi) * NS + kj0] = r;
    }
}

// ---------------------------------------------------------------------------
// Row softmax over 2048 elements. One block (256 thr) per row, 8 elems/thread.
// ---------------------------------------------------------------------------
__global__ void __launch_bounds__(256)
k_softmax(float* attn)
{
    if (!attn) attn = g_attn_fb;
    float* p = attn + (size_t)blockIdx.x * NS;
    const int t = threadIdx.x;

    float4 v0 = ((const float4*)p)[t];
    float4 v1 = ((const float4*)p)[t + 256];

    float m = fmaxf(fmaxf(fmaxf(v0.x, v0.y), fmaxf(v0.z, v0.w)),
                    fmaxf(fmaxf(v1.x, v1.y), fmaxf(v1.z, v1.w)));
    __shared__ float red[256];
    red[t] = m; __syncthreads();
    for (int s = 128; s > 0; s >>= 1) {
        if (t < s) red[t] = fmaxf(red[t], red[t + s]);
        __syncthreads();
    }
    m = red[0];
    __syncthreads();

    float4 e0, e1;
    e0.x = expf(v0.x - m); e0.y = expf(v0.y - m);
    e0.z = expf(v0.z - m); e0.w = expf(v0.w - m);
    e1.x = expf(v1.x - m); e1.y = expf(v1.y - m);
    e1.z = expf(v1.z - m); e1.w = expf(v1.w - m);
    float s8 = e0.x + e0.y + e0.z + e0.w + e1.x + e1.y + e1.z + e1.w;
    red[t] = s8; __syncthreads();
    for (int s = 128; s > 0; s >>= 1) {
        if (t < s) red[t] += red[t + s];
        __syncthreads();
    }
    float inv = 1.f / red[0];

    e0.x *= inv; e0.y *= inv; e0.z *= inv; e0.w *= inv;
    e1.x *= inv; e1.y *= inv; e1.z *= inv; e1.w *= inv;
    ((float4*)p)[t] = e0;
    ((float4*)p)[t + 256] = e1;
}

// ---------------------------------------------------------------------------
// PV: ctx[b,s,h*64+d] = attn[bh] @ v[bh].  64x64 output tile, K=2048 (BK=16).
// ---------------------------------------------------------------------------
__global__ void __launch_bounds__(256)
k_pv(const float* __restrict__ attn_in)
{
    const float* attn = attn_in ? attn_in : g_attn_fb;
    const int bh = blockIdx.y, b = bh >> 3, h = bh & 7;
    const float* A = attn + (size_t)bh * NS * NS + (size_t)blockIdx.x * 64 * NS;
    const float* Vp = g_v + (size_t)bh * NS * ND;

    __shared__ float As[16][64];
    __shared__ float Vs[16][64];

    const int tx = threadIdx.x, ty = threadIdx.y;
    const int tid = ty * 16 + tx;
    const int ar = tid >> 2, ak = (tid & 3) << 2;
    const int br = tid >> 4, bc = (tid & 15) << 2;

    float acc[4][4];
    #pragma unroll
    for (int i = 0; i < 4; i++)
        #pragma unroll
        for (int j = 0; j < 4; j++) acc[i][j] = 0.f;

    for (int k0 = 0; k0 < NS; k0 += 16) {
        float4 av = *(const float4*)&A[(size_t)ar * NS + k0 + ak];
        As[ak+0][ar] = av.x; As[ak+1][ar] = av.y;
        As[ak+2][ar] = av.z; As[ak+3][ar] = av.w;
        *(float4*)&Vs[br][bc] = *(const float4*)&Vp[(size_t)(k0 + br) * ND + bc];
        __syncthreads();
        #pragma unroll
        for (int k = 0; k < 16; k++) {
            float4 a = *(const float4*)&As[k][ty * 4];
            float4 v = *(const float4*)&Vs[k][tx * 4];
            float aa[4] = {a.x, a.y, a.z, a.w};
            float vv[4] = {v.x, v.y, v.z, v.w};
            #pragma unroll
            for (int i = 0; i < 4; i++)
                #pragma unroll
                for (int j = 0; j < 4; j++)
                    acc[i][j] = fmaf(aa[i], vv[j], acc[i][j]);
        }
        __syncthreads();
    }

    #pragma unroll
    for (int i = 0; i < 4; i++) {
        int s = blockIdx.x * 64 + ty * 4 + i;
        float4 r = {acc[i][0], acc[i][1], acc[i][2], acc[i][3]};
        *(float4*)&g_ctx[((size_t)b * NS + s) * NE + h * ND + tx * 4] = r;
    }
}

// ---------------------------------------------------------------------------
// Residual + LayerNorm. One block (128 thr) per row of 512, float4/thread.
// ---------------------------------------------------------------------------
__global__ void __launch_bounds__(128)
k_ln(const float* __restrict__ Qin, const float* __restrict__ gamma,
     const float* __restrict__ beta, float* __restrict__ out)
{
    const int r = blockIdx.x, t = threadIdx.x;
    float4 x = ((const float4*)(g_proj + (size_t)r * NE))[t];
    float4 q = ((const float4*)(Qin + (size_t)r * NE))[t];
    x.x += q.x; x.y += q.y; x.z += q.z; x.w += q.w;

    float s  = x.x + x.y + x.z + x.w;
    float sq = x.x * x.x + x.y * x.y + x.z * x.z + x.w * x.w;

    __shared__ float r1[128], r2[128];
    r1[t] = s; r2[t] = sq; __syncthreads();
    for (int k = 64; k > 0; k >>= 1) {
        if (t < k) { r1[t] += r1[t + k]; r2[t] += r2[t + k]; }
        __syncthreads();
    }
    float mu  = r1[0] * (1.f / NE);
    float var = r2[0] * (1.f / NE) - mu * mu;
    float rs  = rsqrtf(var + 1e-5f);

    float4 g = ((const float4*)gamma)[t];
    float4 bt = ((const float4*)beta)[t];
    float4 o;
    o.x = (x.x - mu) * rs * g.x + bt.x;
    o.y = (x.y - mu) * rs * g.y + bt.y;
    o.z = (x.z - mu) * rs * g.z + bt.z;
    o.w = (x.w - mu) * rs * g.w + bt.w;
    ((float4*)(out + (size_t)r * NE))[t] = o;
}

// ---------------------------------------------------------------------------
extern "C" void kernel_launch(void* const* d_in, const int* in_sizes, int n_in,
                              void* d_out, int out_size)
{
    const float* Q  = (const float*)d_in[0];
    const float* K  = (const float*)d_in[1];
    const float* V  = (const float*)d_in[2];
    const unsigned char* mask = (const unsigned char*)d_in[3];
    const float* Wq = (const float*)d_in[4];
    const float* bq = (const float*)d_in[5];
    const float* Wk = (const float*)d_in[6];
    const float* bk = (const float*)d_in[7];
    const float* Wv = (const float*)d_in[8];
    const float* bv = (const float*)d_in[9];
    const float* Wo = (const float*)d_in[10];
    const float* bo = (const float*)d_in[11];
    const float* gamma = (const float*)d_in[12];
    const float* beta  = (const float*)d_in[13];

    float* out = (float*)d_out;
    const long long outElems  = (long long)NB * NS * NE;
    const long long attnElems = (long long)NBH * NS * NS;
    // attn region of d_out if present (reference returns (out, attn) concatenated);
    // nullptr -> kernels fall back to the static scratch buffer.
    float* attn = ((long long)out_size >= outElems + attnElems) ? (out + outElems)
                                                                : nullptr;

    dim3 blk(16, 16);
    k_proj<<<dim3(8, 128), blk>>>(Q, Wq, bq, 0);
    k_proj<<<dim3(8, 128), blk>>>(K, Wk, bk, 1);
    k_proj<<<dim3(8, 128), blk>>>(V, Wv, bv, 2);
    k_scores<<<dim3(32, 32, NBH), blk>>>(mask, attn);
    k_softmax<<<dim3(NBH * NS), 256>>>(attn);
    k_pv<<<dim3(32, NBH), blk>>>(attn);
    k_proj<<<dim3(8, 128), blk>>>(nullptr, Wo, bo, 3);
    k_ln<<<dim3(NB * NS), 128>>>(Q, gamma, beta, out);
}

// round 2
// speedup vs baseline: 1.7556x; 1.7556x over previous
#include <cuda_runtime.h>
#include <cstdint>

#define NB 4
#define NS 2048
#define NE 512
#define NH 8
#define ND 64
#define NBH (NB*NH)

// Scratch (static device globals: allocation-guard safe)
__device__ float g_q[(size_t)NBH*NS*ND];      // [B,H,S,D]
__device__ float g_k[(size_t)NBH*NS*ND];
__device__ float g_v[(size_t)NBH*NS*ND];
__device__ float g_ctx[(size_t)NB*NS*NE];     // [B,S,H*D]
__device__ float g_proj[(size_t)NB*NS*NE];    // pre-LN output
__device__ float g_attn_fb[(size_t)NBH*NS*NS];// fallback if d_out lacks attn region

// ---------------------------------------------------------------------------
// TF32 helpers
// ---------------------------------------------------------------------------
__device__ __forceinline__ uint32_t f2tf(float x) {
    uint32_t r;
    asm("cvt.rna.tf32.f32 %0, %1;" : "=r"(r) : "f"(x));
    return r;
}

// D = A(16x8,row) * B(8x8,col) + D, tf32 inputs, fp32 accum
__device__ __forceinline__ void mma8(float* c, const uint32_t* a, const uint32_t* b) {
    asm volatile(
        "mma.sync.aligned.m16n8k8.row.col.f32.tf32.tf32.f32 "
        "{%0,%1,%2,%3},{%4,%5,%6,%7},{%8,%9},{%0,%1,%2,%3};"
        : "+f"(c[0]), "+f"(c[1]), "+f"(c[2]), "+f"(c[3])
        : "r"(a[0]), "r"(a[1]), "r"(a[2]), "r"(a[3]), "r"(b[0]), "r"(b[1]));
}

// ---------------------------------------------------------------------------
// Projection GEMM: X[8192,512] @ W[512,512] + bias
// Block tile 128x128, BK=16, 256 threads, 8 warps as 2(m) x 4(n) -> warp 64x32.
// outsel 0/1/2 -> g_q/g_k/g_v as [B,H,S,D]; 3 -> g_proj row-major.
// ---------------------------------------------------------------------------
__global__ void __launch_bounds__(256)
k_proj_mma(const float* __restrict__ Xext, const float* __restrict__ W,
           const float* __restrict__ bias, int outsel)
{
    const float* X = Xext ? Xext : g_ctx;
    float* out = (outsel == 0) ? g_q : (outsel == 1) ? g_k : (outsel == 2) ? g_v : g_proj;

    __shared__ uint32_t As[16][132];   // [k][m], transposed
    __shared__ uint32_t Bs[16][132];   // [k][n]

    const int tid  = threadIdx.x;
    const int lane = tid & 31, warp = tid >> 5;
    const int g    = lane >> 2, tg = lane & 3;
    const int wm   = (warp >> 2) * 64, wn = (warp & 3) * 32;
    const int m0   = blockIdx.y * 128, n0 = blockIdx.x * 128;

    float acc[4][4][4] = {};

    float4 ra[2], rb[2];
    #pragma unroll
    for (int i = 0; i < 2; i++) {
        int f = tid + i * 256;
        ra[i] = *(const float4*)&X[(size_t)(m0 + (f >> 2)) * NE + ((f & 3) << 2)];
        rb[i] = *(const float4*)&W[(size_t)(f >> 5) * NE + n0 + ((f & 31) << 2)];
    }

    for (int k0 = 0; k0 < NE; k0 += 16) {
        #pragma unroll
        for (int i = 0; i < 2; i++) {
            int f = tid + i * 256;
            int r = f >> 2, c4 = (f & 3) << 2;
            As[c4+0][r] = f2tf(ra[i].x); As[c4+1][r] = f2tf(ra[i].y);
            As[c4+2][r] = f2tf(ra[i].z); As[c4+3][r] = f2tf(ra[i].w);
            int br = f >> 5, bc = (f & 31) << 2;
            uint4 t;
            t.x = f2tf(rb[i].x); t.y = f2tf(rb[i].y);
            t.z = f2tf(rb[i].z); t.w = f2tf(rb[i].w);
            *(uint4*)&Bs[br][bc] = t;
        }
        __syncthreads();
        if (k0 + 16 < NE) {
            int k1 = k0 + 16;
            #pragma unroll
            for (int i = 0; i < 2; i++) {
                int f = tid + i * 256;
                ra[i] = *(const float4*)&X[(size_t)(m0 + (f >> 2)) * NE + k1 + ((f & 3) << 2)];
                rb[i] = *(const float4*)&W[(size_t)(k1 + (f >> 5)) * NE + n0 + ((f & 31) << 2)];
            }
        }
        #pragma unroll
        for (int kk = 0; kk < 16; kk += 8) {
            uint32_t af[4][4], bf[4][2];
            #pragma unroll
            for (int mt = 0; mt < 4; mt++) {
                int m = wm + mt * 16 + g;
                af[mt][0] = As[kk+tg  ][m];   af[mt][1] = As[kk+tg  ][m+8];
                af[mt][2] = As[kk+tg+4][m];   af[mt][3] = As[kk+tg+4][m+8];
            }
            #pragma unroll
            for (int nt = 0; nt < 4; nt++) {
                int n = wn + nt * 8 + g;
                bf[nt][0] = Bs[kk+tg][n];  bf[nt][1] = Bs[kk+tg+4][n];
            }
            #pragma unroll
            for (int mt = 0; mt < 4; mt++)
                #pragma unroll
                for (int nt = 0; nt < 4; nt++)
                    mma8(acc[mt][nt], af[mt], bf[nt]);
        }
        __syncthreads();
    }

    #pragma unroll
    for (int mt = 0; mt < 4; mt++) {
        #pragma unroll
        for (int nt = 0; nt < 4; nt++) {
            int n = n0 + wn + nt * 8 + 2 * tg;
            float b0 = bias[n], b1 = bias[n + 1];
            #pragma unroll
            for (int half = 0; half < 2; half++) {
                int m = m0 + wm + mt * 16 + g + half * 8;
                float v0 = acc[mt][nt][half * 2 + 0] + b0;
                float v1 = acc[mt][nt][half * 2 + 1] + b1;
                if (outsel < 3) {
                    int b = m >> 11, s = m & (NS - 1);
                    int h = n >> 6, d = n & 63;
                    *(float2*)&out[(((size_t)(b * NH + h)) * NS + s) * ND + d] =
                        make_float2(v0, v1);
                } else {
                    *(float2*)&out[(size_t)m * NE + n] = make_float2(v0, v1);
                }
            }
        }
    }
}

// ---------------------------------------------------------------------------
// Scores: attn[bh,qi,kj] = (q . k)/8, masked. 128x128 tile, K=64 (BK=32 x2).
// ---------------------------------------------------------------------------
__global__ void __launch_bounds__(256)
k_scores_mma(const unsigned char* __restrict__ mask, float* __restrict__ attn)
{
    if (!attn) attn = g_attn_fb;
    const int bh = blockIdx.z, b = bh >> 3;
    const float* Qp = g_q + (size_t)bh * NS * ND;
    const float* Kp = g_k + (size_t)bh * NS * ND;

    __shared__ uint32_t As[32][132];   // [d][q]
    __shared__ uint32_t Bs[32][132];   // [d][k]

    const int tid  = threadIdx.x;
    const int lane = tid & 31, warp = tid >> 5;
    const int g    = lane >> 2, tg = lane & 3;
    const int wm   = (warp >> 2) * 64, wn = (warp & 3) * 32;
    const int m0   = blockIdx.y * 128, n0 = blockIdx.x * 128;

    float acc[4][4][4] = {};

    for (int k0 = 0; k0 < ND; k0 += 32) {
        #pragma unroll
        for (int i = 0; i < 4; i++) {
            int f = tid + i * 256;
            int r = f >> 3, c4 = (f & 7) << 2;
            float4 qa = *(const float4*)&Qp[(size_t)(m0 + r) * ND + k0 + c4];
            As[c4+0][r] = f2tf(qa.x); As[c4+1][r] = f2tf(qa.y);
            As[c4+2][r] = f2tf(qa.z); As[c4+3][r] = f2tf(qa.w);
            float4 kb = *(const float4*)&Kp[(size_t)(n0 + r) * ND + k0 + c4];
            Bs[c4+0][r] = f2tf(kb.x); Bs[c4+1][r] = f2tf(kb.y);
            Bs[c4+2][r] = f2tf(kb.z); Bs[c4+3][r] = f2tf(kb.w);
        }
        __syncthreads();
        #pragma unroll
        for (int kk = 0; kk < 32; kk += 8) {
            uint32_t af[4][4], bf[4][2];
            #pragma unroll
            for (int mt = 0; mt < 4; mt++) {
                int m = wm + mt * 16 + g;
                af[mt][0] = As[kk+tg  ][m];   af[mt][1] = As[kk+tg  ][m+8];
                af[mt][2] = As[kk+tg+4][m];   af[mt][3] = As[kk+tg+4][m+8];
            }
            #pragma unroll
            for (int nt = 0; nt < 4; nt++) {
                int n = wn + nt * 8 + g;
                bf[nt][0] = Bs[kk+tg][n];  bf[nt][1] = Bs[kk+tg+4][n];
            }
            #pragma unroll
            for (int mt = 0; mt < 4; mt++)
                #pragma unroll
                for (int nt = 0; nt < 4; nt++)
                    mma8(acc[mt][nt], af[mt], bf[nt]);
        }
        __syncthreads();
    }

    #pragma unroll
    for (int mt = 0; mt < 4; mt++) {
        #pragma unroll
        for (int nt = 0; nt < 4; nt++) {
            int kj = n0 + wn + nt * 8 + 2 * tg;
            #pragma unroll
            for (int half = 0; half < 2; half++) {
                int qi = m0 + wm + mt * 16 + g + half * 8;
                uchar2 mv = *(const uchar2*)&mask[((size_t)b * NS + qi) * NS + kj];
                float v0 = mv.x ? -1e9f : acc[mt][nt][half * 2 + 0] * 0.125f;
                float v1 = mv.y ? -1e9f : acc[mt][nt][half * 2 + 1] * 0.125f;
                *(float2*)&attn[((size_t)bh * NS + qi) * NS + kj] = make_float2(v0, v1);
            }
        }
    }
}

// ---------------------------------------------------------------------------
// Row softmax over 2048 elements. One block (256 thr) per row.
// ---------------------------------------------------------------------------
__global__ void __launch_bounds__(256)
k_softmax(float* attn)
{
    if (!attn) attn = g_attn_fb;
    float* p = attn + (size_t)blockIdx.x * NS;
    const int t = threadIdx.x;

    float4 v0 = ((const float4*)p)[t];
    float4 v1 = ((const float4*)p)[t + 256];

    float m = fmaxf(fmaxf(fmaxf(v0.x, v0.y), fmaxf(v0.z, v0.w)),
                    fmaxf(fmaxf(v1.x, v1.y), fmaxf(v1.z, v1.w)));
    __shared__ float red[256];
    red[t] = m; __syncthreads();
    for (int s = 128; s > 0; s >>= 1) {
        if (t < s) red[t] = fmaxf(red[t], red[t + s]);
        __syncthreads();
    }
    m = red[0];
    __syncthreads();

    float4 e0, e1;
    e0.x = expf(v0.x - m); e0.y = expf(v0.y - m);
    e0.z = expf(v0.z - m); e0.w = expf(v0.w - m);
    e1.x = expf(v1.x - m); e1.y = expf(v1.y - m);
    e1.z = expf(v1.z - m); e1.w = expf(v1.w - m);
    float s8 = e0.x + e0.y + e0.z + e0.w + e1.x + e1.y + e1.z + e1.w;
    red[t] = s8; __syncthreads();
    for (int s = 128; s > 0; s >>= 1) {
        if (t < s) red[t] += red[t + s];
        __syncthreads();
    }
    float inv = 1.f / red[0];

    e0.x *= inv; e0.y *= inv; e0.z *= inv; e0.w *= inv;
    e1.x *= inv; e1.y *= inv; e1.z *= inv; e1.w *= inv;
    ((float4*)p)[t] = e0;
    ((float4*)p)[t + 256] = e1;
}

// ---------------------------------------------------------------------------
// PV: ctx = attn @ v. Block 128x64, BK=32, warps 4(m) x 2(n) -> warp 32x32.
// ---------------------------------------------------------------------------
__global__ void __launch_bounds__(256)
k_pv_mma(const float* __restrict__ attn_in)
{
    const float* attn = attn_in ? attn_in : g_attn_fb;
    const int bh = blockIdx.y, b = bh >> 3, h = bh & 7;
    const float* Ap = attn + (size_t)bh * NS * NS;
    const float* Vp = g_v + (size_t)bh * NS * ND;

    __shared__ uint32_t As[32][132];   // [k][m], transposed attn tile
    __shared__ uint32_t Bs[32][68];    // [k][n] v tile

    const int tid  = threadIdx.x;
    const int lane = tid & 31, warp = tid >> 5;
    const int g    = lane >> 2, tg = lane & 3;
    const int wm   = (warp >> 1) * 32, wn = (warp & 1) * 32;
    const int m0   = blockIdx.x * 128;

    float acc[2][4][4] = {};

    float4 ra[4], rb[2];
    #pragma unroll
    for (int i = 0; i < 4; i++) {
        int f = tid + i * 256;
        ra[i] = *(const float4*)&Ap[(size_t)(m0 + (f >> 3)) * NS + ((f & 7) << 2)];
    }
    #pragma unroll
    for (int i = 0; i < 2; i++) {
        int f = tid + i * 256;
        rb[i] = *(const float4*)&Vp[(size_t)(f >> 4) * ND + ((f & 15) << 2)];
    }

    for (int k0 = 0; k0 < NS; k0 += 32) {
        #pragma unroll
        for (int i = 0; i < 4; i++) {
            int f = tid + i * 256;
            int r = f >> 3, c4 = (f & 7) << 2;
            As[c4+0][r] = f2tf(ra[i].x); As[c4+1][r] = f2tf(ra[i].y);
            As[c4+2][r] = f2tf(ra[i].z); As[c4+3][r] = f2tf(ra[i].w);
        }
        #pragma unroll
        for (int i = 0; i < 2; i++) {
            int f = tid + i * 256;
            int br = f >> 4, bc = (f & 15) << 2;
            uint4 t;
            t.x = f2tf(rb[i].x); t.y = f2tf(rb[i].y);
            t.z = f2tf(rb[i].z); t.w = f2tf(rb[i].w);
            *(uint4*)&Bs[br][bc] = t;
        }
        __syncthreads();
        if (k0 + 32 < NS) {
            int k1 = k0 + 32;
            #pragma unroll
            for (int i = 0; i < 4; i++) {
                int f = tid + i * 256;
                ra[i] = *(const float4*)&Ap[(size_t)(m0 + (f >> 3)) * NS + k1 + ((f & 7) << 2)];
            }
            #pragma unroll
            for (int i = 0; i < 2; i++) {
                int f = tid + i * 256;
                rb[i] = *(const float4*)&Vp[(size_t)(k1 + (f >> 4)) * ND + ((f & 15) << 2)];
            }
        }
        #pragma unroll
        for (int kk = 0; kk < 32; kk += 8) {
            uint32_t af[2][4], bf[4][2];
            #pragma unroll
            for (int mt = 0; mt < 2; mt++) {
                int m = wm + mt * 16 + g;
                af[mt][0] = As[kk+tg  ][m];   af[mt][1] = As[kk+tg  ][m+8];
                af[mt][2] = As[kk+tg+4][m];   af[mt][3] = As[kk+tg+4][m+8];
            }
            #pragma unroll
            for (int nt = 0; nt < 4; nt++) {
                int n = wn + nt * 8 + g;
                bf[nt][0] = Bs[kk+tg][n];  bf[nt][1] = Bs[kk+tg+4][n];
            }
            #pragma unroll
            for (int mt = 0; mt < 2; mt++)
                #pragma unroll
                for (int nt = 0; nt < 4; nt++)
                    mma8(acc[mt][nt], af[mt], bf[nt]);
        }
        __syncthreads();
    }

    #pragma unroll
    for (int mt = 0; mt < 2; mt++) {
        #pragma unroll
        for (int nt = 0; nt < 4; nt++) {
            int n = wn + nt * 8 + 2 * tg;
            #pragma unroll
            for (int half = 0; half < 2; half++) {
                int s = m0 + wm + mt * 16 + g + half * 8;
                *(float2*)&g_ctx[((size_t)b * NS + s) * NE + h * ND + n] =
                    make_float2(acc[mt][nt][half * 2 + 0], acc[mt][nt][half * 2 + 1]);
            }
        }
    }
}

// ---------------------------------------------------------------------------
// Residual + LayerNorm. One block (128 thr) per row of 512.
// ---------------------------------------------------------------------------
__global__ void __launch_bounds__(128)
k_ln(const float* __restrict__ Qin, const float* __restrict__ gamma,
     const float* __restrict__ beta, float* __restrict__ out)
{
    const int r = blockIdx.x, t = threadIdx.x;
    float4 x = ((const float4*)(g_proj + (size_t)r * NE))[t];
    float4 q = ((const float4*)(Qin + (size_t)r * NE))[t];
    x.x += q.x; x.y += q.y; x.z += q.z; x.w += q.w;

    float s  = x.x + x.y + x.z + x.w;
    float sq = x.x * x.x + x.y * x.y + x.z * x.z + x.w * x.w;

    __shared__ float r1[128], r2[128];
    r1[t] = s; r2[t] = sq; __syncthreads();
    for (int k = 64; k > 0; k >>= 1) {
        if (t < k) { r1[t] += r1[t + k]; r2[t] += r2[t + k]; }
        __syncthreads();
    }
    float mu  = r1[0] * (1.f / NE);
    float var = r2[0] * (1.f / NE) - mu * mu;
    float rs  = rsqrtf(var + 1e-5f);

    float4 gm = ((const float4*)gamma)[t];
    float4 bt = ((const float4*)beta)[t];
    float4 o;
    o.x = (x.x - mu) * rs * gm.x + bt.x;
    o.y = (x.y - mu) * rs * gm.y + bt.y;
    o.z = (x.z - mu) * rs * gm.z + bt.z;
    o.w = (x.w - mu) * rs * gm.w + bt.w;
    ((float4*)(out + (size_t)r * NE))[t] = o;
}

// ---------------------------------------------------------------------------
extern "C" void kernel_launch(void* const* d_in, const int* in_sizes, int n_in,
                              void* d_out, int out_size)
{
    const float* Q  = (const float*)d_in[0];
    const float* K  = (const float*)d_in[1];
    const float* V  = (const float*)d_in[2];
    const unsigned char* mask = (const unsigned char*)d_in[3];
    const float* Wq = (const float*)d_in[4];
    const float* bq = (const float*)d_in[5];
    const float* Wk = (const float*)d_in[6];
    const float* bk = (const float*)d_in[7];
    const float* Wv = (const float*)d_in[8];
    const float* bv = (const float*)d_in[9];
    const float* Wo = (const float*)d_in[10];
    const float* bo = (const float*)d_in[11];
    const float* gamma = (const float*)d_in[12];
    const float* beta  = (const float*)d_in[13];

    float* out = (float*)d_out;
    const long long outElems  = (long long)NB * NS * NE;
    const long long attnElems = (long long)NBH * NS * NS;
    float* attn = ((long long)out_size >= outElems + attnElems) ? (out + outElems)
                                                                : nullptr;

    k_proj_mma<<<dim3(4, 64), 256>>>(Q, Wq, bq, 0);
    k_proj_mma<<<dim3(4, 64), 256>>>(K, Wk, bk, 1);
    k_proj_mma<<<dim3(4, 64), 256>>>(V, Wv, bv, 2);
    k_scores_mma<<<dim3(16, 16, NBH), 256>>>(mask, attn);
    k_softmax<<<dim3(NBH * NS), 256>>>(attn);
    k_pv_mma<<<dim3(16, NBH), 256>>>(attn);
    k_proj_mma<<<dim3(4, 64), 256>>>(nullptr, Wo, bo, 3);
    k_ln<<<dim3(NB * NS), 128>>>(Q, gamma, beta, out);
}

// round 3
// speedup vs baseline: 2.1086x; 1.2011x over previous
#include <cuda_runtime.h>
#include <cuda_fp16.h>
#include <cstdint>

#define NB 4
#define NS 2048
#define NE 512
#define NH 8
#define ND 64
#define NBH (NB*NH)

// Scratch (static device globals: allocation-guard safe)
__device__ __half g_qh[(size_t)NBH*NS*ND];     // [B,H,S,D] fp16
__device__ __half g_kh[(size_t)NBH*NS*ND];
__device__ __half g_vh[(size_t)NBH*NS*ND];
__device__ __half g_ctx_h[(size_t)NB*NS*NE];   // [B,S,H*D] fp16
__device__ float  g_proj[(size_t)NB*NS*NE];    // pre-LN output fp32
__device__ float  g_pm[(size_t)NBH*16*NS];     // per-(bh, ktile, row) max partial
__device__ float  g_ps[(size_t)NBH*16*NS];     // per-(bh, ktile, row) sumexp partial
__device__ float  g_attn_fb[(size_t)NBH*NS*NS];// fallback if d_out lacks attn region

// ---------------------------------------------------------------------------
// MMA / ldmatrix helpers (fp16 in, fp32 accum)
// ---------------------------------------------------------------------------
__device__ __forceinline__ void ldsm4(uint32_t* r, const void* p) {
    uint32_t a = (uint32_t)__cvta_generic_to_shared(p);
    asm volatile("ldmatrix.sync.aligned.m8n8.x4.shared.b16 {%0,%1,%2,%3}, [%4];"
        : "=r"(r[0]), "=r"(r[1]), "=r"(r[2]), "=r"(r[3]) : "r"(a));
}
__device__ __forceinline__ void ldsm4t(uint32_t* r, const void* p) {
    uint32_t a = (uint32_t)__cvta_generic_to_shared(p);
    asm volatile("ldmatrix.sync.aligned.m8n8.x4.trans.shared.b16 {%0,%1,%2,%3}, [%4];"
        : "=r"(r[0]), "=r"(r[1]), "=r"(r[2]), "=r"(r[3]) : "r"(a));
}
__device__ __forceinline__ void mma16816(float* c, const uint32_t* a, const uint32_t* b) {
    asm volatile(
        "mma.sync.aligned.m16n8k16.row.col.f32.f16.f16.f32 "
        "{%0,%1,%2,%3},{%4,%5,%6,%7},{%8,%9},{%0,%1,%2,%3};"
        : "+f"(c[0]), "+f"(c[1]), "+f"(c[2]), "+f"(c[3])
        : "r"(a[0]), "r"(a[1]), "r"(a[2]), "r"(a[3]), "r"(b[0]), "r"(b[1]));
}
__device__ __forceinline__ uint32_t pkh2(float x, float y) {
    __half2 h = __floats2half2_rn(x, y);
    return *(uint32_t*)&h;
}

// ---------------------------------------------------------------------------
// QKV projection: X[8192,512]f32 @ W[512,512]f32 + b -> fp16 [B,H,S,D]
// 128x128 tile, BK=32, 256 thr, warps 2m x 4n (warp 64x32).
// ---------------------------------------------------------------------------
__global__ void __launch_bounds__(256)
k_projQKV(const float* __restrict__ X, const float* __restrict__ W,
          const float* __restrict__ bias, int outsel)
{
    __half* out = (outsel == 0) ? g_qh : (outsel == 1) ? g_kh : g_vh;
    __shared__ __half As[128][40];
    __shared__ __half Bs[32][136];

    const int tid = threadIdx.x, lane = tid & 31, warp = tid >> 5;
    const int g = lane >> 2, tg = lane & 3;
    const int wm = (warp >> 2) * 64, wn = (warp & 3) * 32;
    const int m0 = blockIdx.y * 128, n0 = blockIdx.x * 128;

    float acc[4][4][4] = {};

    for (int k0 = 0; k0 < NE; k0 += 32) {
        #pragma unroll
        for (int i = 0; i < 4; i++) {
            int f = tid + i * 256;
            int r = f >> 3, c4 = (f & 7) << 2;
            float4 v = *(const float4*)&X[(size_t)(m0 + r) * NE + k0 + c4];
            *(uint2*)&As[r][c4] = make_uint2(pkh2(v.x, v.y), pkh2(v.z, v.w));
        }
        #pragma unroll
        for (int i = 0; i < 4; i++) {
            int f = tid + i * 256;
            int kr = f >> 5, nc4 = (f & 31) << 2;
            float4 v = *(const float4*)&W[(size_t)(k0 + kr) * NE + n0 + nc4];
            *(uint2*)&Bs[kr][nc4] = make_uint2(pkh2(v.x, v.y), pkh2(v.z, v.w));
        }
        __syncthreads();
        #pragma unroll
        for (int kk = 0; kk < 32; kk += 16) {
            uint32_t af[4][4], bf[2][4];
            #pragma unroll
            for (int mt = 0; mt < 4; mt++)
                ldsm4(af[mt], &As[wm + mt*16 + (lane & 7) + ((lane >> 3) & 1) * 8]
                                 [kk + ((lane >> 4) & 1) * 8]);
            #pragma unroll
            for (int p = 0; p < 2; p++)
                ldsm4t(bf[p], &Bs[kk + ((lane >> 3) & 1) * 8 + (lane & 7)]
                                  [wn + p*16 + ((lane >> 4) & 1) * 8]);
            #pragma unroll
            for (int mt = 0; mt < 4; mt++)
                #pragma unroll
                for (int nt = 0; nt < 4; nt++)
                    mma16816(acc[mt][nt], af[mt], &bf[nt >> 1][(nt & 1) * 2]);
        }
        __syncthreads();
    }

    #pragma unroll
    for (int mt = 0; mt < 4; mt++) {
        #pragma unroll
        for (int nt = 0; nt < 4; nt++) {
            int n = n0 + wn + nt * 8 + 2 * tg;
            float b0 = bias[n], b1 = bias[n + 1];
            int h = n >> 6, d = n & 63;
            #pragma unroll
            for (int half = 0; half < 2; half++) {
                int m = m0 + wm + mt * 16 + g + half * 8;
                int b = m >> 11, s = m & (NS - 1);
                __half2 hv = __floats2half2_rn(acc[mt][nt][half*2] + b0,
                                               acc[mt][nt][half*2+1] + b1);
                *(__half2*)&out[(((size_t)(b * NH + h)) * NS + s) * ND + d] = hv;
            }
        }
    }
}

// ---------------------------------------------------------------------------
// Output projection: ctx_h[8192,512]f16 @ Wo[512,512]f32 + bo -> g_proj f32
// ---------------------------------------------------------------------------
__global__ void __launch_bounds__(256)
k_oproj(const float* __restrict__ W, const float* __restrict__ bias)
{
    __shared__ __half As[128][40];
    __shared__ __half Bs[32][136];

    const int tid = threadIdx.x, lane = tid & 31, warp = tid >> 5;
    const int g = lane >> 2, tg = lane & 3;
    const int wm = (warp >> 2) * 64, wn = (warp & 3) * 32;
    const int m0 = blockIdx.y * 128, n0 = blockIdx.x * 128;

    float acc[4][4][4] = {};

    for (int k0 = 0; k0 < NE; k0 += 32) {
        #pragma unroll
        for (int i = 0; i < 2; i++) {
            int f = tid + i * 256;
            int r = f >> 2, c8 = (f & 3) << 3;
            *(uint4*)&As[r][c8] =
                *(const uint4*)&g_ctx_h[(size_t)(m0 + r) * NE + k0 + c8];
        }
        #pragma unroll
        for (int i = 0; i < 4; i++) {
            int f = tid + i * 256;
            int kr = f >> 5, nc4 = (f & 31) << 2;
            float4 v = *(const float4*)&W[(size_t)(k0 + kr) * NE + n0 + nc4];
            *(uint2*)&Bs[kr][nc4] = make_uint2(pkh2(v.x, v.y), pkh2(v.z, v.w));
        }
        __syncthreads();
        #pragma unroll
        for (int kk = 0; kk < 32; kk += 16) {
            uint32_t af[4][4], bf[2][4];
            #pragma unroll
            for (int mt = 0; mt < 4; mt++)
                ldsm4(af[mt], &As[wm + mt*16 + (lane & 7) + ((lane >> 3) & 1) * 8]
                                 [kk + ((lane >> 4) & 1) * 8]);
            #pragma unroll
            for (int p = 0; p < 2; p++)
                ldsm4t(bf[p], &Bs[kk + ((lane >> 3) & 1) * 8 + (lane & 7)]
                                  [wn + p*16 + ((lane >> 4) & 1) * 8]);
            #pragma unroll
            for (int mt = 0; mt < 4; mt++)
                #pragma unroll
                for (int nt = 0; nt < 4; nt++)
                    mma16816(acc[mt][nt], af[mt], &bf[nt >> 1][(nt & 1) * 2]);
        }
        __syncthreads();
    }

    #pragma unroll
    for (int mt = 0; mt < 4; mt++) {
        #pragma unroll
        for (int nt = 0; nt < 4; nt++) {
            int n = n0 + wn + nt * 8 + 2 * tg;
            float b0 = bias[n], b1 = bias[n + 1];
            #pragma unroll
            for (int half = 0; half < 2; half++) {
                int m = m0 + wm + mt * 16 + g + half * 8;
                *(float2*)&g_proj[(size_t)m * NE + n] =
                    make_float2(acc[mt][nt][half*2] + b0, acc[mt][nt][half*2+1] + b1);
            }
        }
    }
}

// ---------------------------------------------------------------------------
// Scores + row-stats: attn[bh,qi,kj] = masked (q.k)/8 ; per-row (max,sumexp)
// partials per 128-col block -> g_pm/g_ps. 128x128 tile, K=64 in one shot.
// ---------------------------------------------------------------------------
__global__ void __launch_bounds__(256)
k_scores(const unsigned char* __restrict__ mask, float* __restrict__ attn)
{
    if (!attn) attn = g_attn_fb;
    const int bh = blockIdx.z, b = bh >> 3;
    const __half* Qp = g_qh + (size_t)bh * NS * ND;
    const __half* Kp = g_kh + (size_t)bh * NS * ND;

    __shared__ __half Qs[128][72];
    __shared__ __half Ks[128][72];
    __shared__ float sm_m[4][128];
    __shared__ float sm_s[4][128];

    const int tid = threadIdx.x, lane = tid & 31, warp = tid >> 5;
    const int g = lane >> 2, tg = lane & 3;
    const int wm = (warp >> 2) * 64, wn = (warp & 3) * 32;
    const int wnid = warp & 3;
    const int m0 = blockIdx.y * 128, n0 = blockIdx.x * 128;

    #pragma unroll
    for (int i = 0; i < 4; i++) {
        int f = tid + i * 256;
        int r = f >> 3, c8 = (f & 7) << 3;
        *(uint4*)&Qs[r][c8] = *(const uint4*)&Qp[(size_t)(m0 + r) * ND + c8];
        *(uint4*)&Ks[r][c8] = *(const uint4*)&Kp[(size_t)(n0 + r) * ND + c8];
    }
    __syncthreads();

    float acc[4][4][4] = {};
    #pragma unroll
    for (int kk = 0; kk < 64; kk += 16) {
        uint32_t af[4][4], bf[2][4];
        #pragma unroll
        for (int mt = 0; mt < 4; mt++)
            ldsm4(af[mt], &Qs[wm + mt*16 + (lane & 7) + ((lane >> 3) & 1) * 8]
                             [kk + ((lane >> 4) & 1) * 8]);
        #pragma unroll
        for (int p = 0; p < 2; p++)
            ldsm4(bf[p], &Ks[wn + p*16 + ((lane >> 4) & 1) * 8 + (lane & 7)]
                            [kk + ((lane >> 3) & 1) * 8]);
        #pragma unroll
        for (int mt = 0; mt < 4; mt++)
            #pragma unroll
            for (int nt = 0; nt < 4; nt++)
                mma16816(acc[mt][nt], af[mt], &bf[nt >> 1][(nt & 1) * 2]);
    }

    // epilogue: mask + scale + write, and per-row (m, sumexp) stats
    #pragma unroll
    for (int mt = 0; mt < 4; mt++) {
        #pragma unroll
        for (int half = 0; half < 2; half++) {
            int qloc = wm + mt * 16 + g + half * 8;
            int qi = m0 + qloc;
            float vv[8];
            #pragma unroll
            for (int nt = 0; nt < 4; nt++) {
                int kj = n0 + wn + nt * 8 + 2 * tg;
                uchar2 mv = *(const uchar2*)&mask[((size_t)b * NS + qi) * NS + kj];
                float v0 = mv.x ? -1e9f : acc[mt][nt][half*2+0] * 0.125f;
                float v1 = mv.y ? -1e9f : acc[mt][nt][half*2+1] * 0.125f;
                *(float2*)&attn[((size_t)bh * NS + qi) * NS + kj] = make_float2(v0, v1);
                vv[nt*2] = v0; vv[nt*2+1] = v1;
            }
            float m = vv[0];
            #pragma unroll
            for (int j = 1; j < 8; j++) m = fmaxf(m, vv[j]);
            float s = 0.f;
            #pragma unroll
            for (int j = 0; j < 8; j++) s += __expf(vv[j] - m);
            #pragma unroll
            for (int d_ = 1; d_ < 4; d_ <<= 1) {
                float om = __shfl_xor_sync(0xffffffffu, m, d_);
                float os = __shfl_xor_sync(0xffffffffu, s, d_);
                float nm = fmaxf(m, om);
                s = s * __expf(m - nm) + os * __expf(om - nm);
                m = nm;
            }
            if (tg == 0) { sm_m[wnid][qloc] = m; sm_s[wnid][qloc] = s; }
        }
    }
    __syncthreads();
    if (tid < 128) {
        float m = sm_m[0][tid], s = sm_s[0][tid];
        #pragma unroll
        for (int w = 1; w < 4; w++) {
            float om = sm_m[w][tid], os = sm_s[w][tid];
            float nm = fmaxf(m, om);
            s = s * __expf(m - nm) + os * __expf(om - nm);
            m = nm;
        }
        size_t idx = ((size_t)bh * 16 + blockIdx.x) * NS + m0 + tid;
        g_pm[idx] = m; g_ps[idx] = s;
    }
}

// ---------------------------------------------------------------------------
// Fused normalize + PV: combine row stats, read raw scores, write normalized
// probs in place, accumulate P@V -> ctx_h (fp16).
// Block: q-tile 128, loop k in tiles of 64. Warps 2m x 4n (warp 64x16).
// ---------------------------------------------------------------------------
__global__ void __launch_bounds__(256)
k_npv(float* __restrict__ attn)
{
    if (!attn) attn = g_attn_fb;
    const int bh = blockIdx.y, b = bh >> 3, h = bh & 7;
    const int m0 = blockIdx.x * 128;
    const __half* Vp = g_vh + (size_t)bh * NS * ND;
    float* Ap = attn + (size_t)bh * NS * NS;

    __shared__ __half Ps[128][72];
    __shared__ __half Vs[64][72];
    __shared__ float sm_m[128];
    __shared__ float sm_i[128];

    const int tid = threadIdx.x, lane = tid & 31, warp = tid >> 5;
    const int g = lane >> 2, tg = lane & 3;
    const int wm = (warp >> 2) * 64, wn = (warp & 3) * 16;

    if (tid < 128) {
        float m = -3.4e38f, s = 0.f;
        for (int j = 0; j < 16; j++) {
            size_t idx = ((size_t)bh * 16 + j) * NS + m0 + tid;
            float om = g_pm[idx], os = g_ps[idx];
            float nm = fmaxf(m, om);
            s = s * __expf(m - nm) + os * __expf(om - nm);
            m = nm;
        }
        sm_m[tid] = m; sm_i[tid] = 1.f / s;
    }
    __syncthreads();

    float acc[4][2][4] = {};

    for (int kt = 0; kt < NS; kt += 64) {
        #pragma unroll
        for (int i = 0; i < 8; i++) {
            int f = tid + i * 256;
            int r = f >> 4, c4 = (f & 15) << 2;
            float4 v = *(float4*)&Ap[(size_t)(m0 + r) * NS + kt + c4];
            float m = sm_m[r], inv = sm_i[r];
            v.x = __expf(v.x - m) * inv;
            v.y = __expf(v.y - m) * inv;
            v.z = __expf(v.z - m) * inv;
            v.w = __expf(v.w - m) * inv;
            *(float4*)&Ap[(size_t)(m0 + r) * NS + kt + c4] = v;
            *(uint2*)&Ps[r][c4] = make_uint2(pkh2(v.x, v.y), pkh2(v.z, v.w));
        }
        #pragma unroll
        for (int i = 0; i < 2; i++) {
            int f = tid + i * 256;
            int r = f >> 3, c8 = (f & 7) << 3;
            *(uint4*)&Vs[r][c8] = *(const uint4*)&Vp[(size_t)(kt + r) * ND + c8];
        }
        __syncthreads();
        #pragma unroll
        for (int kk = 0; kk < 64; kk += 16) {
            uint32_t af[4][4], bf[4];
            #pragma unroll
            for (int mt = 0; mt < 4; mt++)
                ldsm4(af[mt], &Ps[wm + mt*16 + (lane & 7) + ((lane >> 3) & 1) * 8]
                                 [kk + ((lane >> 4) & 1) * 8]);
            ldsm4t(bf, &Vs[kk + ((lane >> 3) & 1) * 8 + (lane & 7)]
                          [wn + ((lane >> 4) & 1) * 8]);
            #pragma unroll
            for (int mt = 0; mt < 4; mt++)
                #pragma unroll
                for (int nt = 0; nt < 2; nt++)
                    mma16816(acc[mt][nt], af[mt], &bf[nt * 2]);
        }
        __syncthreads();
    }

    #pragma unroll
    for (int mt = 0; mt < 4; mt++) {
        #pragma unroll
        for (int nt = 0; nt < 2; nt++) {
            int n = wn + nt * 8 + 2 * tg;
            #pragma unroll
            for (int half = 0; half < 2; half++) {
                int s = m0 + wm + mt * 16 + g + half * 8;
                __half2 hv = __floats2half2_rn(acc[mt][nt][half*2],
                                               acc[mt][nt][half*2+1]);
                *(__half2*)&g_ctx_h[((size_t)b * NS + s) * NE + h * ND + n] = hv;
            }
        }
    }
}

// ---------------------------------------------------------------------------
// Residual + LayerNorm. One block (128 thr) per row of 512.
// ---------------------------------------------------------------------------
__global__ void __launch_bounds__(128)
k_ln(const float* __restrict__ Qin, const float* __restrict__ gamma,
     const float* __restrict__ beta, float* __restrict__ out)
{
    const int r = blockIdx.x, t = threadIdx.x;
    float4 x = ((const float4*)(g_proj + (size_t)r * NE))[t];
    float4 q = ((const float4*)(Qin + (size_t)r * NE))[t];
    x.x += q.x; x.y += q.y; x.z += q.z; x.w += q.w;

    float s  = x.x + x.y + x.z + x.w;
    float sq = x.x * x.x + x.y * x.y + x.z * x.z + x.w * x.w;

    __shared__ float r1[128], r2[128];
    r1[t] = s; r2[t] = sq; __syncthreads();
    for (int k = 64; k > 0; k >>= 1) {
        if (t < k) { r1[t] += r1[t + k]; r2[t] += r2[t + k]; }
        __syncthreads();
    }
    float mu  = r1[0] * (1.f / NE);
    float var = r2[0] * (1.f / NE) - mu * mu;
    float rs  = rsqrtf(var + 1e-5f);

    float4 gm = ((const float4*)gamma)[t];
    float4 bt = ((const float4*)beta)[t];
    float4 o;
    o.x = (x.x - mu) * rs * gm.x + bt.x;
    o.y = (x.y - mu) * rs * gm.y + bt.y;
    o.z = (x.z - mu) * rs * gm.z + bt.z;
    o.w = (x.w - mu) * rs * gm.w + bt.w;
    ((float4*)(out + (size_t)r * NE))[t] = o;
}

// ---------------------------------------------------------------------------
extern "C" void kernel_launch(void* const* d_in, const int* in_sizes, int n_in,
                              void* d_out, int out_size)
{
    const float* Q  = (const float*)d_in[0];
    const float* K  = (const float*)d_in[1];
    const float* V  = (const float*)d_in[2];
    const unsigned char* mask = (const unsigned char*)d_in[3];
    const float* Wq = (const float*)d_in[4];
    const float* bq = (const float*)d_in[5];
    const float* Wk = (const float*)d_in[6];
    const float* bk = (const float*)d_in[7];
    const float* Wv = (const float*)d_in[8];
    const float* bv = (const float*)d_in[9];
    const float* Wo = (const float*)d_in[10];
    const float* bo = (const float*)d_in[11];
    const float* gamma = (const float*)d_in[12];
    const float* beta  = (const float*)d_in[13];

    float* out = (float*)d_out;
    const long long outElems  = (long long)NB * NS * NE;
    const long long attnElems = (long long)NBH * NS * NS;
    float* attn = ((long long)out_size >= outElems + attnElems) ? (out + outElems)
                                                                : nullptr;

    k_projQKV<<<dim3(4, 64), 256>>>(Q, Wq, bq, 0);
    k_projQKV<<<dim3(4, 64), 256>>>(K, Wk, bk, 1);
    k_projQKV<<<dim3(4, 64), 256>>>(V, Wv, bv, 2);
    k_scores<<<dim3(16, 16, NBH), 256>>>(mask, attn);
    k_npv<<<dim3(16, NBH), 256>>>(attn);
    k_oproj<<<dim3(4, 64), 256>>>(Wo, bo);
    k_ln<<<dim3(NB * NS), 128>>>(Q, gamma, beta, out);
}